// round 12
// baseline (speedup 1.0000x reference)
#include <cuda_runtime.h>
#include <cstdint>
#include <math.h>

#define Bq 64
#define Sq 384
#define Eq 64
#define Dq 50
#define Gq 256   // 4*E
#define ST 66    // h_sm row stride
#define SL 192   // attention rows per cluster CTA (Sq/2)

// scratch (allocation-free rule: __device__ globals)
__device__ float g_h1[Bq*Sq*Eq];
__device__ float g_c1[Bq*Sq*Eq];
__device__ float g_out[Bq*Sq*Eq];
__device__ float g_base[Bq*Sq*Eq];
__device__ float g_Rt[Bq*Sq*Eq];
__device__ float g_xp1[Bq*Sq*Gq];
__device__ float g_xp2[Bq*Sq*Gq];

// ---- fast transcendentals (err ~1e-6, well under the 1e-3 gate) ----------
__device__ __forceinline__ float rcp_fast(float x){
    float r; asm("rcp.approx.f32 %0, %1;" : "=f"(r) : "f"(x)); return r;
}
__device__ __forceinline__ float ftanh(float x){
    float t = __expf(-2.f * fabsf(x));
    float y = (1.f - t) * rcp_fast(1.f + t);
    return copysignf(y, x);
}
__device__ __forceinline__ float fsig(float x){
    return rcp_fast(1.f + __expf(-x));
}
__device__ __forceinline__ uint32_t smem_u32(const void* p){
    uint32_t a;
    asm("{ .reg .u64 t; cvta.to.shared.u64 t, %1; cvt.u32.u64 %0, t; }"
        : "=r"(a) : "l"(p));
    return a;
}
__device__ __forceinline__ uint32_t mapa_u32(uint32_t addr, uint32_t rank){
    uint32_t r;
    asm("mapa.shared::cluster.u32 %0, %1, %2;" : "=r"(r) : "r"(addr), "r"(rank));
    return r;
}
__device__ __forceinline__ void st_cluster_f32(uint32_t addr, float v){
    asm volatile("st.shared::cluster.f32 [%0], %1;" :: "r"(addr), "f"(v) : "memory");
}
__device__ __forceinline__ void mbar_init(uint32_t addr, uint32_t count){
    asm volatile("mbarrier.init.shared.b64 [%0], %1;" :: "r"(addr), "r"(count) : "memory");
}
__device__ __forceinline__ void mbar_arrive_remote(uint32_t addr){
    asm volatile("mbarrier.arrive.release.cluster.shared::cluster.b64 _, [%0];"
                 :: "r"(addr) : "memory");
}
__device__ __forceinline__ void mbar_wait_parity(uint32_t addr, uint32_t parity){
    uint32_t done;
    asm volatile(
        "{\n\t.reg .pred p;\n\t"
        "mbarrier.try_wait.parity.acquire.cluster.shared::cta.b64 p, [%1], %2;\n\t"
        "selp.b32 %0, 1, 0, p;\n\t}"
        : "=r"(done) : "r"(addr), "r"(parity) : "memory");
    while (!done) {
        asm volatile(
            "{\n\t.reg .pred p;\n\t"
            "mbarrier.try_wait.parity.acquire.cluster.shared::cta.b64 p, [%1], %2, 0x989680;\n\t"
            "selp.b32 %0, 1, 0, p;\n\t}"
            : "=r"(done) : "r"(addr), "r"(parity) : "memory");
    }
}
__device__ __forceinline__ void cluster_sync(){
    asm volatile("barrier.cluster.arrive.aligned;" ::: "memory");
    asm volatile("barrier.cluster.wait.aligned;"   ::: "memory");
}
__device__ __forceinline__ void named_bar(int id, int count){
    asm volatile("bar.sync %0, %1;" :: "r"(id), "r"(count) : "memory");
}

// ---------------------------------------------------------------------------
// Input projection: xp[b,s,g] = emb[tok[b,s]] @ Wih[g,:] + bih[g] + bhh[g]
// ---------------------------------------------------------------------------
__global__ __launch_bounds__(256) void xproj_kernel(
    const int* __restrict__ toks, const float* __restrict__ emb,
    const float* __restrict__ Wih, const float* __restrict__ bih,
    const float* __restrict__ bhh, float* __restrict__ xp)
{
    __shared__ float xs[32][Dq];
    __shared__ int   tk[32];
    int row0 = blockIdx.x * 32;
    int j = threadIdx.x;

    if (j < 32) tk[j] = toks[row0 + j];
    __syncthreads();
    for (int i = j; i < 32*Dq; i += 256) {
        int r = i / Dq, k = i % Dq;
        xs[r][k] = emb[tk[r]*Dq + k];
    }

    float w[Dq];
#pragma unroll
    for (int k = 0; k < Dq; k++) w[k] = Wih[j*Dq + k];
    float bias = bih[j] + bhh[j];
    __syncthreads();

#pragma unroll 4
    for (int r = 0; r < 32; r++) {
        float acc = bias;
#pragma unroll
        for (int k = 0; k < Dq; k++) acc += w[k]*xs[r][k];
        xp[(row0 + r)*Gq + j] = acc;
    }
}

// ---------------------------------------------------------------------------
// Recurrent LSTM: TWO independent batch rows per CTA (grid Bq/2, 512 thr).
// Half `sub` (threads sub*256..+255) runs batch b = 2*blockIdx.x + sub with
// its own named barrier (id 1+sub, count 256) — the two latency-bound chains
// interleave on the SM's schedulers, hiding each other's stalls.
// Per half: R6 shape + hoisted gate nonlinearity.
// ---------------------------------------------------------------------------
__global__ __launch_bounds__(512) void lstm_kernel(
    const float* __restrict__ xp, const float* __restrict__ Whh,
    const int* __restrict__ iidx, int mode)
{
    __shared__ __align__(16) float hs[2][Eq];
    __shared__ float gs[2][Gq];

    int tid = threadIdx.x;
    int sub = tid >> 8;                  // 0 or 1
    int j   = tid & 255;                 // gate row within half
    int b   = blockIdx.x*2 + sub;
    int ty  = j >> 6;                    // gate type: 0=i 1=f 2=g 3=o
    int bar = 1 + sub;

    float* oh = mode ? g_out : g_h1;
    float* oc = mode ? nullptr : g_c1;

    float whh[Eq];
#pragma unroll
    for (int k = 0; k < Eq; k++) whh[k] = Whh[j*Eq + k];

    float c = 0.f;
    if (j < Eq) {
        float h0 = 0.f;
        if (mode) {
            int idx = iidx[b*Eq + j];          // s1_len is (B,1,E)
            h0 = g_h1[(b*Sq + idx)*Eq + j];
            c  = g_c1[(b*Sq + idx)*Eq + j];
        }
        hs[sub][j] = h0;
    }
    named_bar(bar, 256);

    const float* xpb = xp + (size_t)b*Sq*Gq + j;
    float xv = xpb[0];

    for (int t = 0; t < Sq; t++) {
        const float4* h4 = (const float4*)hs[sub];
        float a0 = xv, a1 = 0.f, a2 = 0.f, a3 = 0.f;
#pragma unroll
        for (int k = 0; k < 4; k++) {
            float4 v0 = h4[4*k], v1 = h4[4*k+1], v2 = h4[4*k+2], v3 = h4[4*k+3];
            a0 += whh[16*k   ]*v0.x + whh[16*k+1 ]*v0.y + whh[16*k+2 ]*v0.z + whh[16*k+3 ]*v0.w;
            a1 += whh[16*k+4 ]*v1.x + whh[16*k+5 ]*v1.y + whh[16*k+6 ]*v1.z + whh[16*k+7 ]*v1.w;
            a2 += whh[16*k+8 ]*v2.x + whh[16*k+9 ]*v2.y + whh[16*k+10]*v2.z + whh[16*k+11]*v2.w;
            a3 += whh[16*k+12]*v3.x + whh[16*k+13]*v3.y + whh[16*k+14]*v3.z + whh[16*k+15]*v3.w;
        }
        float acc = (a0 + a1) + (a2 + a3);
        if (t + 1 < Sq) xv = xpb[(t+1)*Gq];    // prefetch next gate input
        // hoisted nonlinearity: parallel across all 8 warps of this half
        gs[sub][j] = (ty == 2) ? ftanh(acc) : fsig(acc);
        named_bar(bar, 256);

        if (j < Eq) {
            float ig = gs[sub][j];
            float fg = gs[sub][Eq + j];
            float gg = gs[sub][2*Eq + j];
            float og = gs[sub][3*Eq + j];
            c = fg*c + ig*gg;
            float h = og*ftanh(c);
            hs[sub][j] = h;
            oh[(b*Sq + t)*Eq + j] = h;
            if (oc) oc[(b*Sq + t)*Eq + j] = c;
        }
        named_bar(bar, 256);
    }
}

// ---------------------------------------------------------------------------
// base[b,s,:] = h1[b,s,:] @ wy + out[b,s,:] @ wh
// ---------------------------------------------------------------------------
__global__ __launch_bounds__(256) void base_kernel(
    const float* __restrict__ wy, const float* __restrict__ wh)
{
    __shared__ float wys[Eq*Eq], whs[Eq*Eq];
    __shared__ float ht[16][Eq], ot[16][Eq];

    int b  = blockIdx.y;
    int s0 = blockIdx.x * 16;
    int tid = threadIdx.x;

    for (int i = tid; i < Eq*Eq; i += 256) { wys[i] = wy[i]; whs[i] = wh[i]; }
    for (int i = tid; i < 16*Eq; i += 256) {
        int s = i >> 6, k = i & 63;
        ht[s][k] = g_h1 [(b*Sq + s0 + s)*Eq + k];
        ot[s][k] = g_out[(b*Sq + s0 + s)*Eq + k];
    }
    __syncthreads();

    int sl = tid >> 4;
    int e0 = (tid & 15) * 4;
    float acc[4] = {0.f, 0.f, 0.f, 0.f};
#pragma unroll 8
    for (int k = 0; k < Eq; k++) {
        float hv = ht[sl][k], ov = ot[sl][k];
#pragma unroll
        for (int u = 0; u < 4; u++)
            acc[u] += hv*wys[k*Eq + e0 + u] + ov*whs[k*Eq + e0 + u];
    }
    float* dst = &g_base[(b*Sq + s0 + sl)*Eq + e0];
#pragma unroll
    for (int u = 0; u < 4; u++) dst[u] = acc[u];
}

// ---------------------------------------------------------------------------
// Attention scan (best-measured shape), 2-CTA cluster per batch row.
// tb (raw tanh(base)) and wtb = w*tb REGISTER-resident (loop-invariant).
// p1 exports tr (raw) and wtr = w*tr; p2 per elem:
//   sc += (wtb + wtr) * rcp(1 + tb*tr)   [tanh addition identity]
// Partials pushed into PEER smem via st.shared::cluster + remote mbar arrive.
// ---------------------------------------------------------------------------
#define ATT_FLOATS (4 + 2*68 + SL*ST + 4*64 + 12*64 + 16)
#define ATT_SMEM   (ATT_FLOATS*4)

__global__ __launch_bounds__(384) __cluster_dims__(2, 1, 1)
void attn_kernel(
    const float* __restrict__ wvec, const float* __restrict__ wr,
    const float* __restrict__ wt,   const float* __restrict__ s1s)
{
    extern __shared__ float sm[];
    // sm[0..3]: mbarrier (8B) + pad
    float* imp    = sm + 4;              // 2*68 import slots (peer writes here)
    float* h_sm   = imp + 2*68;          // SL*ST
    float* r_s    = h_sm + SL*ST;        // 64 (16B aligned)
    float* tr_s   = r_s + 64;            // 64  raw tanh(r@wr)
    float* wtr_s  = tr_s + 64;           // 64  w*tanh(r@wr)
    float* trwt_s = wtr_s + 64;          // 64  tanh(r@wt)
    float* part   = trwt_s + 64;         // 12*64
    float* red    = part + 12*64;        // 16

    int cta  = blockIdx.x;
    int b    = cta >> 1;
    uint32_t rank = cta & 1u;
    int tid  = threadIdx.x;
    int lane = tid & 31, wid = tid >> 5;

    uint32_t mbar_local  = smem_u32(sm);
    uint32_t mbar_remote = mapa_u32(mbar_local, rank ^ 1u);
    uint32_t imp_remote  = mapa_u32(smem_u32(imp), rank ^ 1u);

    if (tid == 0) mbar_init(mbar_local, 64);

    int half = lane & 1;
    int row  = wid*16 + (lane >> 1);     // p2 row for this thread (0..191)

    // p1 weights: thread tid<256 -> output o=tid>>1, rows hh*32..+32
    float wcol[32];
    float wv_o = 0.f;
    if (tid < 256) {
        int o = tid >> 1, hh = tid & 1;
        const float* wsrc = (o < 64) ? (wr + o) : (wt + o - 64);
#pragma unroll
        for (int k = 0; k < 32; k++) wcol[k] = wsrc[(hh*32 + k)*Eq];
        if (o < 64 && hh == 0) wv_o = wvec[o];
    }

    const int gofs = b*Sq*Eq + (int)rank*SL*Eq;
    for (int i = tid; i < SL*Eq; i += 384) {
        int s = i >> 6, e = i & 63;
        h_sm[s*ST + e] = g_h1[gofs + i];
    }
    // loop-invariant per-thread registers: raw tb and w-scaled wtb
    float tb[32], wtb[32];
    {
        const float* bsrc = &g_base[gofs + row*Eq + half*32];
        const float* wsrc = wvec + half*32;
#pragma unroll
        for (int k = 0; k < 32; k++) {
            tb[k]  = ftanh(bsrc[k]);
            wtb[k] = wsrc[k]*tb[k];
        }
    }
    float m1 = s1s[b*Sq + (int)rank*SL + row];
    if (tid < 64) r_s[tid] = 0.f;
    __syncthreads();
    cluster_sync();   // peer's mbarrier init visible before any remote arrive

    for (int t = 0; t < Sq; t++) {
        // p1: tr = tanh(r@wr) (+ w-scaled), trwt = tanh(r@wt); 2 thr/output
        if (tid < 256) {
            int o = tid >> 1, hh = tid & 1;
            const float4* r4 = (const float4*)(r_s + hh*32);
            float a0 = 0.f, a1 = 0.f;
#pragma unroll
            for (int q = 0; q < 8; q += 2) {
                float4 v0 = r4[q], v1 = r4[q+1];
                a0 += wcol[4*q  ]*v0.x + wcol[4*q+1]*v0.y
                    + wcol[4*q+2]*v0.z + wcol[4*q+3]*v0.w;
                a1 += wcol[4*q+4]*v1.x + wcol[4*q+5]*v1.y
                    + wcol[4*q+6]*v1.z + wcol[4*q+7]*v1.w;
            }
            float s_ = a0 + a1;
            s_ += __shfl_xor_sync(0xffffffffu, s_, 1);
            if (hh == 0) {
                float v = ftanh(s_);
                if (o < 64) { tr_s[o] = v; wtr_s[o] = wv_o*v; }
                else trwt_s[o-64] = v;
            }
        }
        __syncthreads();

        // p2: score for `row` (2 threads/row, 32 elems each)
        float sc = 0.f;
        {
            const float4* tr4 = (const float4*)(tr_s  + half*32);
            const float4* wr4 = (const float4*)(wtr_s + half*32);
#pragma unroll
            for (int q = 0; q < 8; q++) {
                float4 tv = tr4[q], wv = wr4[q];
                float d0 = rcp_fast(fmaf(tb[4*q  ], tv.x, 1.f));
                float d1 = rcp_fast(fmaf(tb[4*q+1], tv.y, 1.f));
                float d2 = rcp_fast(fmaf(tb[4*q+2], tv.z, 1.f));
                float d3 = rcp_fast(fmaf(tb[4*q+3], tv.w, 1.f));
                sc = fmaf(wtb[4*q  ] + wv.x, d0, sc);
                sc = fmaf(wtb[4*q+1] + wv.y, d1, sc);
                sc = fmaf(wtb[4*q+2] + wv.z, d2, sc);
                sc = fmaf(wtb[4*q+3] + wv.w, d3, sc);
            }
        }
        sc += __shfl_xor_sync(0xffffffffu, sc, 1);
        sc = m1*sc - (1.f - m1)*1e12f;
        float p = __expf(sc);

        // warp sum of p (each p duplicated in a lane pair -> halve)
        float v = p;
#pragma unroll
        for (int o = 16; o > 0; o >>= 1) v += __shfl_xor_sync(0xffffffffu, v, o);
        if (lane == 0) red[wid] = 0.5f*v;

        // p3: h.p partials for this warp's 16 rows; lane covers 2 e-columns
        {
            int e2 = lane*2;
            float a0 = 0.f, a1 = 0.f;
            const float* hb = &h_sm[(wid*16)*ST + e2];
#pragma unroll
            for (int si = 0; si < 16; si++) {
                float pv = __shfl_sync(0xffffffffu, p, 2*si);
                float2 hv = *(const float2*)&hb[si*ST];
                a0 += hv.x * pv; a1 += hv.y * pv;
            }
            part[wid*64 + e2]     = a0;
            part[wid*64 + e2 + 1] = a1;
        }
        __syncthreads();

        // p5: combine partials, exchange with peer, update r
        if (tid < 64) {
            float nl = 0.f;
#pragma unroll
            for (int g = 0; g < 12; g++) nl += part[g*64 + tid];
            float sl_ = 0.f;
#pragma unroll
            for (int i = 0; i < 12; i++) sl_ += red[i];

            int slot = (t & 1) * 68;
            st_cluster_f32(imp_remote + (slot + tid)*4, nl);
            if (tid == 0) st_cluster_f32(imp_remote + (slot + 64)*4, sl_);
            mbar_arrive_remote(mbar_remote);           // release (64 arrivals)
            mbar_wait_parity(mbar_local, (uint32_t)(t & 1));

            float pn = imp[slot + tid];
            float ps = imp[slot + 64];
            float rn = (nl + pn)*rcp_fast(sl_ + ps) + trwt_s[tid];
            r_s[tid] = rn;
            if (rank == 0) g_Rt[(b*Sq + t)*Eq + tid] = rn;
        }
        __syncthreads();
    }
    cluster_sync();   // no CTA exits while peer may still write our smem
}

// ---------------------------------------------------------------------------
// Final gathers + MLP head
// ---------------------------------------------------------------------------
__global__ __launch_bounds__(128) void final_kernel(
    const int* __restrict__ s2len,
    const float* __restrict__ wp, const float* __restrict__ wx,
    const float* __restrict__ l1W, const float* __restrict__ l1b,
    const float* __restrict__ lW,  const float* __restrict__ lb,
    float* __restrict__ outp)
{
    __shared__ float rn[64], hn[64], hid[64], h2[128];
    int b = blockIdx.x, tid = threadIdx.x;

    if (tid < 64) {
        int idx = s2len[b*64 + tid];
        rn[tid] = g_Rt [(b*Sq + idx)*Eq + tid];
        hn[tid] = g_out[(b*Sq + idx)*Eq + tid];
    }
    __syncthreads();
    if (tid < 64) {
        float a = 0.f;
#pragma unroll 8
        for (int e = 0; e < 64; e++)
            a += rn[e]*wp[e*64 + tid] + hn[e]*wx[e*64 + tid];
        hid[tid] = ftanh(a);
    }
    __syncthreads();
    {
        float a = l1b[tid];
#pragma unroll 8
        for (int f = 0; f < 64; f++) a += hid[f]*l1W[tid*64 + f];
        h2[tid] = ftanh(a);
    }
    __syncthreads();
    if (tid < 4) {
        float a = lb[tid];
#pragma unroll 8
        for (int j = 0; j < 128; j++) a += h2[j]*lW[tid*128 + j];
        outp[b*4 + tid] = a;
    }
}

// ---------------------------------------------------------------------------
extern "C" void kernel_launch(void* const* d_in, const int* in_sizes, int n_in,
                              void* d_out, int out_size)
{
    (void)in_sizes; (void)n_in; (void)out_size;

    const int*   s1   = (const int*)d_in[0];
    const int*   s2   = (const int*)d_in[1];
    const int*   s1l  = (const int*)d_in[2];
    const int*   s2l  = (const int*)d_in[3];
    const float* s1s  = (const float*)d_in[4];
    /* d_in[5] = s2_s, unused by the reference */
    const float* emb  = (const float*)d_in[6];
    const float* Wih1 = (const float*)d_in[7];
    const float* Whh1 = (const float*)d_in[8];
    const float* bih1 = (const float*)d_in[9];
    const float* bhh1 = (const float*)d_in[10];
    const float* Wih2 = (const float*)d_in[11];
    const float* Whh2 = (const float*)d_in[12];
    const float* bih2 = (const float*)d_in[13];
    const float* bhh2 = (const float*)d_in[14];
    const float* wy   = (const float*)d_in[15];
    const float* wh   = (const float*)d_in[16];
    const float* wv   = (const float*)d_in[17];
    const float* wp   = (const float*)d_in[18];
    const float* wx   = (const float*)d_in[19];
    const float* wr   = (const float*)d_in[20];
    const float* wt   = (const float*)d_in[21];
    const float* l1W  = (const float*)d_in[22];
    const float* l1b  = (const float*)d_in[23];
    const float* lW   = (const float*)d_in[24];
    const float* lb   = (const float*)d_in[25];
    float* outp = (float*)d_out;

    cudaFuncSetAttribute(attn_kernel,
                         cudaFuncAttributeMaxDynamicSharedMemorySize, ATT_SMEM);

    float* xp1; cudaGetSymbolAddress((void**)&xp1, g_xp1);
    float* xp2; cudaGetSymbolAddress((void**)&xp2, g_xp2);

    xproj_kernel<<<(Bq*Sq)/32, 256>>>(s1, emb, Wih1, bih1, bhh1, xp1);
    xproj_kernel<<<(Bq*Sq)/32, 256>>>(s2, emb, Wih2, bih2, bhh2, xp2);
    lstm_kernel<<<Bq/2, 512>>>(xp1, Whh1, nullptr, 0);
    lstm_kernel<<<Bq/2, 512>>>(xp2, Whh2, s1l, 1);
    base_kernel<<<dim3(24, Bq), 256>>>(wy, wh);
    attn_kernel<<<Bq*2, 384, ATT_SMEM>>>(wv, wr, wt, s1s);
    final_kernel<<<Bq, 128>>>(s2l, wp, wx, l1W, l1b, lW, lb, outp);
}

// round 13
// speedup vs baseline: 1.2117x; 1.2117x over previous
#include <cuda_runtime.h>
#include <cstdint>
#include <math.h>

#define Bq 64
#define Sq 384
#define Eq 64
#define Dq 50
#define Gq 256   // 4*E
#define ST 66    // h_sm row stride
#define SL 192   // attention rows per cluster CTA (Sq/2)

// scratch (allocation-free rule: __device__ globals)
__device__ float g_h1[Bq*Sq*Eq];
__device__ float g_c1[Bq*Sq*Eq];
__device__ float g_out[Bq*Sq*Eq];
__device__ float g_base[Bq*Sq*Eq];
__device__ float g_Rt[Bq*Sq*Eq];
__device__ float g_xp1[Bq*Sq*Gq];
__device__ float g_xp2[Bq*Sq*Gq];

// ---- fast transcendentals (err ~1e-6, well under the 1e-3 gate) ----------
__device__ __forceinline__ float rcp_fast(float x){
    float r; asm("rcp.approx.f32 %0, %1;" : "=f"(r) : "f"(x)); return r;
}
__device__ __forceinline__ float ftanh(float x){
    float t = __expf(-2.f * fabsf(x));
    float y = (1.f - t) * rcp_fast(1.f + t);
    return copysignf(y, x);
}
__device__ __forceinline__ float fsig(float x){
    return rcp_fast(1.f + __expf(-x));
}
__device__ __forceinline__ uint32_t smem_u32(const void* p){
    uint32_t a;
    asm("{ .reg .u64 t; cvta.to.shared.u64 t, %1; cvt.u32.u64 %0, t; }"
        : "=r"(a) : "l"(p));
    return a;
}
__device__ __forceinline__ uint32_t mapa_u32(uint32_t addr, uint32_t rank){
    uint32_t r;
    asm("mapa.shared::cluster.u32 %0, %1, %2;" : "=r"(r) : "r"(addr), "r"(rank));
    return r;
}
__device__ __forceinline__ void st_cluster_f32(uint32_t addr, float v){
    asm volatile("st.shared::cluster.f32 [%0], %1;" :: "r"(addr), "f"(v) : "memory");
}
__device__ __forceinline__ void mbar_init(uint32_t addr, uint32_t count){
    asm volatile("mbarrier.init.shared.b64 [%0], %1;" :: "r"(addr), "r"(count) : "memory");
}
__device__ __forceinline__ void mbar_arrive_remote(uint32_t addr){
    asm volatile("mbarrier.arrive.release.cluster.shared::cluster.b64 _, [%0];"
                 :: "r"(addr) : "memory");
}
__device__ __forceinline__ void mbar_wait_parity(uint32_t addr, uint32_t parity){
    uint32_t done;
    asm volatile(
        "{\n\t.reg .pred p;\n\t"
        "mbarrier.try_wait.parity.acquire.cluster.shared::cta.b64 p, [%1], %2;\n\t"
        "selp.b32 %0, 1, 0, p;\n\t}"
        : "=r"(done) : "r"(addr), "r"(parity) : "memory");
    while (!done) {
        asm volatile(
            "{\n\t.reg .pred p;\n\t"
            "mbarrier.try_wait.parity.acquire.cluster.shared::cta.b64 p, [%1], %2, 0x989680;\n\t"
            "selp.b32 %0, 1, 0, p;\n\t}"
            : "=r"(done) : "r"(addr), "r"(parity) : "memory");
    }
}
__device__ __forceinline__ void cluster_sync(){
    asm volatile("barrier.cluster.arrive.aligned;" ::: "memory");
    asm volatile("barrier.cluster.wait.aligned;"   ::: "memory");
}

// ---------------------------------------------------------------------------
// Input projection: xp[b,s,g] = emb[tok[b,s]] @ Wih[g,:] + bih[g] + bhh[g]
// ---------------------------------------------------------------------------
__global__ __launch_bounds__(256) void xproj_kernel(
    const int* __restrict__ toks, const float* __restrict__ emb,
    const float* __restrict__ Wih, const float* __restrict__ bih,
    const float* __restrict__ bhh, float* __restrict__ xp)
{
    __shared__ float xs[32][Dq];
    __shared__ int   tk[32];
    int row0 = blockIdx.x * 32;
    int j = threadIdx.x;

    if (j < 32) tk[j] = toks[row0 + j];
    __syncthreads();
    for (int i = j; i < 32*Dq; i += 256) {
        int r = i / Dq, k = i % Dq;
        xs[r][k] = emb[tk[r]*Dq + k];
    }

    float w[Dq];
#pragma unroll
    for (int k = 0; k < Dq; k++) w[k] = Wih[j*Dq + k];
    float bias = bih[j] + bhh[j];
    __syncthreads();

#pragma unroll 4
    for (int r = 0; r < 32; r++) {
        float acc = bias;
#pragma unroll
        for (int k = 0; k < Dq; k++) acc += w[k]*xs[r][k];
        xp[(row0 + r)*Gq + j] = acc;
    }
}

// ---------------------------------------------------------------------------
// Recurrent LSTM (R6 exact — best measured): one CTA per b, 256 threads.
// ---------------------------------------------------------------------------
__global__ __launch_bounds__(256) void lstm_kernel(
    const float* __restrict__ xp, const float* __restrict__ Whh,
    const int* __restrict__ iidx, int mode)
{
    __shared__ __align__(16) float hs[Eq];
    __shared__ float gs[Gq];

    int b = blockIdx.x, j = threadIdx.x;
    float* oh = mode ? g_out : g_h1;
    float* oc = mode ? nullptr : g_c1;

    float whh[Eq];
#pragma unroll
    for (int k = 0; k < Eq; k++) whh[k] = Whh[j*Eq + k];

    float c = 0.f;
    if (j < Eq) {
        float h0 = 0.f;
        if (mode) {
            int idx = iidx[b*Eq + j];          // s1_len is (B,1,E)
            h0 = g_h1[(b*Sq + idx)*Eq + j];
            c  = g_c1[(b*Sq + idx)*Eq + j];
        }
        hs[j] = h0;
    }
    __syncthreads();

    const float* xpb = xp + (size_t)b*Sq*Gq + j;
    float xv = xpb[0];

    for (int t = 0; t < Sq; t++) {
        const float4* h4 = (const float4*)hs;
        float a0 = xv, a1 = 0.f, a2 = 0.f, a3 = 0.f;
#pragma unroll
        for (int k = 0; k < 4; k++) {
            float4 v0 = h4[4*k], v1 = h4[4*k+1], v2 = h4[4*k+2], v3 = h4[4*k+3];
            a0 += whh[16*k   ]*v0.x + whh[16*k+1 ]*v0.y + whh[16*k+2 ]*v0.z + whh[16*k+3 ]*v0.w;
            a1 += whh[16*k+4 ]*v1.x + whh[16*k+5 ]*v1.y + whh[16*k+6 ]*v1.z + whh[16*k+7 ]*v1.w;
            a2 += whh[16*k+8 ]*v2.x + whh[16*k+9 ]*v2.y + whh[16*k+10]*v2.z + whh[16*k+11]*v2.w;
            a3 += whh[16*k+12]*v3.x + whh[16*k+13]*v3.y + whh[16*k+14]*v3.z + whh[16*k+15]*v3.w;
        }
        float acc = (a0 + a1) + (a2 + a3);
        if (t + 1 < Sq) xv = xpb[(t+1)*Gq];    // prefetch next gate input
        gs[j] = acc;
        __syncthreads();

        if (j < Eq) {
            float ig = fsig(gs[j]);
            float fg = fsig(gs[Eq + j]);
            float gg = ftanh(gs[2*Eq + j]);
            float og = fsig(gs[3*Eq + j]);
            c = fg*c + ig*gg;
            float h = og*ftanh(c);
            hs[j] = h;
            oh[(b*Sq + t)*Eq + j] = h;
            if (oc) oc[(b*Sq + t)*Eq + j] = c;
        }
        __syncthreads();
    }
}

// ---------------------------------------------------------------------------
// base[b,s,:] = h1[b,s,:] @ wy + out[b,s,:] @ wh
// ---------------------------------------------------------------------------
__global__ __launch_bounds__(256) void base_kernel(
    const float* __restrict__ wy, const float* __restrict__ wh)
{
    __shared__ float wys[Eq*Eq], whs[Eq*Eq];
    __shared__ float ht[16][Eq], ot[16][Eq];

    int b  = blockIdx.y;
    int s0 = blockIdx.x * 16;
    int tid = threadIdx.x;

    for (int i = tid; i < Eq*Eq; i += 256) { wys[i] = wy[i]; whs[i] = wh[i]; }
    for (int i = tid; i < 16*Eq; i += 256) {
        int s = i >> 6, k = i & 63;
        ht[s][k] = g_h1 [(b*Sq + s0 + s)*Eq + k];
        ot[s][k] = g_out[(b*Sq + s0 + s)*Eq + k];
    }
    __syncthreads();

    int sl = tid >> 4;
    int e0 = (tid & 15) * 4;
    float acc[4] = {0.f, 0.f, 0.f, 0.f};
#pragma unroll 8
    for (int k = 0; k < Eq; k++) {
        float hv = ht[sl][k], ov = ot[sl][k];
#pragma unroll
        for (int u = 0; u < 4; u++)
            acc[u] += hv*wys[k*Eq + e0 + u] + ov*whs[k*Eq + e0 + u];
    }
    float* dst = &g_base[(b*Sq + s0 + sl)*Eq + e0];
#pragma unroll
    for (int u = 0; u < 4; u++) dst[u] = acc[u];
}

// ---------------------------------------------------------------------------
// Attention scan, 2-CTA cluster per batch row (best-measured shape).
// p2 uses QUAD-RCP batching: 4 quotients share one rcp.approx:
//   sum wa_i/b_i = ((wa0*b1+wa1*b0)*b2b3 + (wa2*b3+wa3*b2)*b0b1) * rcp(b0b1*b2b3)
// where b_i = 1 + tb_i*tr_i, wa_i = wtb_i + wtr_i   [tanh addition identity]
// MUFU per thread-step: 32 -> 8. b in (0,2], products <= 16 — safe.
// ---------------------------------------------------------------------------
#define ATT_FLOATS (4 + 2*68 + SL*ST + 4*64 + 12*64 + 16)
#define ATT_SMEM   (ATT_FLOATS*4)

__global__ __launch_bounds__(384) __cluster_dims__(2, 1, 1)
void attn_kernel(
    const float* __restrict__ wvec, const float* __restrict__ wr,
    const float* __restrict__ wt,   const float* __restrict__ s1s)
{
    extern __shared__ float sm[];
    // sm[0..3]: mbarrier (8B) + pad
    float* imp    = sm + 4;              // 2*68 import slots (peer writes here)
    float* h_sm   = imp + 2*68;          // SL*ST
    float* r_s    = h_sm + SL*ST;        // 64 (16B aligned)
    float* tr_s   = r_s + 64;            // 64  raw tanh(r@wr)
    float* wtr_s  = tr_s + 64;           // 64  w*tanh(r@wr)
    float* trwt_s = wtr_s + 64;          // 64  tanh(r@wt)
    float* part   = trwt_s + 64;         // 12*64
    float* red    = part + 12*64;        // 16

    int cta  = blockIdx.x;
    int b    = cta >> 1;
    uint32_t rank = cta & 1u;
    int tid  = threadIdx.x;
    int lane = tid & 31, wid = tid >> 5;

    uint32_t mbar_local  = smem_u32(sm);
    uint32_t mbar_remote = mapa_u32(mbar_local, rank ^ 1u);
    uint32_t imp_remote  = mapa_u32(smem_u32(imp), rank ^ 1u);

    if (tid == 0) mbar_init(mbar_local, 64);

    int half = lane & 1;
    int row  = wid*16 + (lane >> 1);     // p2 row for this thread (0..191)

    // p1 weights: thread tid<256 -> output o=tid>>1, rows hh*32..+32
    float wcol[32];
    float wv_o = 0.f;
    if (tid < 256) {
        int o = tid >> 1, hh = tid & 1;
        const float* wsrc = (o < 64) ? (wr + o) : (wt + o - 64);
#pragma unroll
        for (int k = 0; k < 32; k++) wcol[k] = wsrc[(hh*32 + k)*Eq];
        if (o < 64 && hh == 0) wv_o = wvec[o];
    }

    const int gofs = b*Sq*Eq + (int)rank*SL*Eq;
    for (int i = tid; i < SL*Eq; i += 384) {
        int s = i >> 6, e = i & 63;
        h_sm[s*ST + e] = g_h1[gofs + i];
    }
    // loop-invariant per-thread registers: raw tb and w-scaled wtb
    float tb[32], wtb[32];
    {
        const float* bsrc = &g_base[gofs + row*Eq + half*32];
        const float* wsrc = wvec + half*32;
#pragma unroll
        for (int k = 0; k < 32; k++) {
            tb[k]  = ftanh(bsrc[k]);
            wtb[k] = wsrc[k]*tb[k];
        }
    }
    float m1 = s1s[b*Sq + (int)rank*SL + row];
    if (tid < 64) r_s[tid] = 0.f;
    __syncthreads();
    cluster_sync();   // peer's mbarrier init visible before any remote arrive

    for (int t = 0; t < Sq; t++) {
        // p1: tr = tanh(r@wr) (+ w-scaled), trwt = tanh(r@wt); 2 thr/output
        if (tid < 256) {
            int o = tid >> 1, hh = tid & 1;
            const float4* r4 = (const float4*)(r_s + hh*32);
            float a0 = 0.f, a1 = 0.f;
#pragma unroll
            for (int q = 0; q < 8; q += 2) {
                float4 v0 = r4[q], v1 = r4[q+1];
                a0 += wcol[4*q  ]*v0.x + wcol[4*q+1]*v0.y
                    + wcol[4*q+2]*v0.z + wcol[4*q+3]*v0.w;
                a1 += wcol[4*q+4]*v1.x + wcol[4*q+5]*v1.y
                    + wcol[4*q+6]*v1.z + wcol[4*q+7]*v1.w;
            }
            float s_ = a0 + a1;
            s_ += __shfl_xor_sync(0xffffffffu, s_, 1);
            if (hh == 0) {
                float v = ftanh(s_);
                if (o < 64) { tr_s[o] = v; wtr_s[o] = wv_o*v; }
                else trwt_s[o-64] = v;
            }
        }
        __syncthreads();

        // p2: score for `row` (2 threads/row, 32 elems each), quad-rcp form
        float sc = 0.f;
        {
            const float4* tr4 = (const float4*)(tr_s  + half*32);
            const float4* wr4 = (const float4*)(wtr_s + half*32);
#pragma unroll
            for (int q = 0; q < 8; q++) {
                float4 tv = tr4[q], wv = wr4[q];
                float b0 = fmaf(tb[4*q  ], tv.x, 1.f);
                float b1 = fmaf(tb[4*q+1], tv.y, 1.f);
                float b2 = fmaf(tb[4*q+2], tv.z, 1.f);
                float b3 = fmaf(tb[4*q+3], tv.w, 1.f);
                float wa0 = wtb[4*q  ] + wv.x;
                float wa1 = wtb[4*q+1] + wv.y;
                float wa2 = wtb[4*q+2] + wv.z;
                float wa3 = wtb[4*q+3] + wv.w;
                float n01 = fmaf(wa1, b0, wa0*b1);
                float n23 = fmaf(wa3, b2, wa2*b3);
                float d01 = b0*b1, d23 = b2*b3;
                float num = fmaf(n23, d01, n01*d23);
                sc = fmaf(num, rcp_fast(d01*d23), sc);
            }
        }
        sc += __shfl_xor_sync(0xffffffffu, sc, 1);
        sc = m1*sc - (1.f - m1)*1e12f;
        float p = __expf(sc);

        // warp sum of p (each p duplicated in a lane pair -> halve)
        float v = p;
#pragma unroll
        for (int o = 16; o > 0; o >>= 1) v += __shfl_xor_sync(0xffffffffu, v, o);
        if (lane == 0) red[wid] = 0.5f*v;

        // p3: h.p partials for this warp's 16 rows; lane covers 2 e-columns
        {
            int e2 = lane*2;
            float a0 = 0.f, a1 = 0.f;
            const float* hb = &h_sm[(wid*16)*ST + e2];
#pragma unroll
            for (int si = 0; si < 16; si++) {
                float pv = __shfl_sync(0xffffffffu, p, 2*si);
                float2 hv = *(const float2*)&hb[si*ST];
                a0 += hv.x * pv; a1 += hv.y * pv;
            }
            part[wid*64 + e2]     = a0;
            part[wid*64 + e2 + 1] = a1;
        }
        __syncthreads();

        // p5: combine partials, exchange with peer, update r
        if (tid < 64) {
            float nl = 0.f;
#pragma unroll
            for (int g = 0; g < 12; g++) nl += part[g*64 + tid];
            float sl_ = 0.f;
#pragma unroll
            for (int i = 0; i < 12; i++) sl_ += red[i];

            int slot = (t & 1) * 68;
            st_cluster_f32(imp_remote + (slot + tid)*4, nl);
            if (tid == 0) st_cluster_f32(imp_remote + (slot + 64)*4, sl_);
            mbar_arrive_remote(mbar_remote);           // release (64 arrivals)
            mbar_wait_parity(mbar_local, (uint32_t)(t & 1));

            float pn = imp[slot + tid];
            float ps = imp[slot + 64];
            float rn = (nl + pn)*rcp_fast(sl_ + ps) + trwt_s[tid];
            r_s[tid] = rn;
            if (rank == 0) g_Rt[(b*Sq + t)*Eq + tid] = rn;
        }
        __syncthreads();
    }
    cluster_sync();   // no CTA exits while peer may still write our smem
}

// ---------------------------------------------------------------------------
// Final gathers + MLP head
// ---------------------------------------------------------------------------
__global__ __launch_bounds__(128) void final_kernel(
    const int* __restrict__ s2len,
    const float* __restrict__ wp, const float* __restrict__ wx,
    const float* __restrict__ l1W, const float* __restrict__ l1b,
    const float* __restrict__ lW,  const float* __restrict__ lb,
    float* __restrict__ outp)
{
    __shared__ float rn[64], hn[64], hid[64], h2[128];
    int b = blockIdx.x, tid = threadIdx.x;

    if (tid < 64) {
        int idx = s2len[b*64 + tid];
        rn[tid] = g_Rt [(b*Sq + idx)*Eq + tid];
        hn[tid] = g_out[(b*Sq + idx)*Eq + tid];
    }
    __syncthreads();
    if (tid < 64) {
        float a = 0.f;
#pragma unroll 8
        for (int e = 0; e < 64; e++)
            a += rn[e]*wp[e*64 + tid] + hn[e]*wx[e*64 + tid];
        hid[tid] = ftanh(a);
    }
    __syncthreads();
    {
        float a = l1b[tid];
#pragma unroll 8
        for (int f = 0; f < 64; f++) a += hid[f]*l1W[tid*64 + f];
        h2[tid] = ftanh(a);
    }
    __syncthreads();
    if (tid < 4) {
        float a = lb[tid];
#pragma unroll 8
        for (int j = 0; j < 128; j++) a += h2[j]*lW[tid*128 + j];
        outp[b*4 + tid] = a;
    }
}

// ---------------------------------------------------------------------------
extern "C" void kernel_launch(void* const* d_in, const int* in_sizes, int n_in,
                              void* d_out, int out_size)
{
    (void)in_sizes; (void)n_in; (void)out_size;

    const int*   s1   = (const int*)d_in[0];
    const int*   s2   = (const int*)d_in[1];
    const int*   s1l  = (const int*)d_in[2];
    const int*   s2l  = (const int*)d_in[3];
    const float* s1s  = (const float*)d_in[4];
    /* d_in[5] = s2_s, unused by the reference */
    const float* emb  = (const float*)d_in[6];
    const float* Wih1 = (const float*)d_in[7];
    const float* Whh1 = (const float*)d_in[8];
    const float* bih1 = (const float*)d_in[9];
    const float* bhh1 = (const float*)d_in[10];
    const float* Wih2 = (const float*)d_in[11];
    const float* Whh2 = (const float*)d_in[12];
    const float* bih2 = (const float*)d_in[13];
    const float* bhh2 = (const float*)d_in[14];
    const float* wy   = (const float*)d_in[15];
    const float* wh   = (const float*)d_in[16];
    const float* wv   = (const float*)d_in[17];
    const float* wp   = (const float*)d_in[18];
    const float* wx   = (const float*)d_in[19];
    const float* wr   = (const float*)d_in[20];
    const float* wt   = (const float*)d_in[21];
    const float* l1W  = (const float*)d_in[22];
    const float* l1b  = (const float*)d_in[23];
    const float* lW   = (const float*)d_in[24];
    const float* lb   = (const float*)d_in[25];
    float* outp = (float*)d_out;

    cudaFuncSetAttribute(attn_kernel,
                         cudaFuncAttributeMaxDynamicSharedMemorySize, ATT_SMEM);

    float* xp1; cudaGetSymbolAddress((void**)&xp1, g_xp1);
    float* xp2; cudaGetSymbolAddress((void**)&xp2, g_xp2);

    xproj_kernel<<<(Bq*Sq)/32, 256>>>(s1, emb, Wih1, bih1, bhh1, xp1);
    xproj_kernel<<<(Bq*Sq)/32, 256>>>(s2, emb, Wih2, bih2, bhh2, xp2);
    lstm_kernel<<<Bq, 256>>>(xp1, Whh1, nullptr, 0);
    lstm_kernel<<<Bq, 256>>>(xp2, Whh2, s1l, 1);
    base_kernel<<<dim3(24, Bq), 256>>>(wy, wh);
    attn_kernel<<<Bq*2, 384, ATT_SMEM>>>(wv, wr, wt, s1s);
    final_kernel<<<Bq, 128>>>(s2l, wp, wx, l1W, l1b, lW, lb, outp);
}

// round 14
// speedup vs baseline: 1.3113x; 1.0822x over previous
#include <cuda_runtime.h>
#include <cstdint>
#include <math.h>

#define Bq 64
#define Sq 384
#define Eq 64
#define Dq 50
#define Gq 256   // 4*E
#define SL 192   // attention rows per cluster CTA (Sq/2)

// scratch (allocation-free rule: __device__ globals)
__device__ float g_h1[Bq*Sq*Eq];
__device__ float g_c1[Bq*Sq*Eq];
__device__ float g_out[Bq*Sq*Eq];
__device__ float g_base[Bq*Sq*Eq];
__device__ float g_Rt[Bq*Sq*Eq];
__device__ float g_xp1[Bq*Sq*Gq];
__device__ float g_xp2[Bq*Sq*Gq];

// ---- fast transcendentals (err ~1e-6, well under the 1e-3 gate) ----------
__device__ __forceinline__ float rcp_fast(float x){
    float r; asm("rcp.approx.f32 %0, %1;" : "=f"(r) : "f"(x)); return r;
}
__device__ __forceinline__ float ftanh(float x){
    float t = __expf(-2.f * fabsf(x));
    float y = (1.f - t) * rcp_fast(1.f + t);
    return copysignf(y, x);
}
__device__ __forceinline__ float fsig(float x){
    return rcp_fast(1.f + __expf(-x));
}
__device__ __forceinline__ uint32_t smem_u32(const void* p){
    uint32_t a;
    asm("{ .reg .u64 t; cvta.to.shared.u64 t, %1; cvt.u32.u64 %0, t; }"
        : "=r"(a) : "l"(p));
    return a;
}
__device__ __forceinline__ uint32_t mapa_u32(uint32_t addr, uint32_t rank){
    uint32_t r;
    asm("mapa.shared::cluster.u32 %0, %1, %2;" : "=r"(r) : "r"(addr), "r"(rank));
    return r;
}
__device__ __forceinline__ void st_cluster_f32(uint32_t addr, float v){
    asm volatile("st.shared::cluster.f32 [%0], %1;" :: "r"(addr), "f"(v) : "memory");
}
__device__ __forceinline__ void mbar_init(uint32_t addr, uint32_t count){
    asm volatile("mbarrier.init.shared.b64 [%0], %1;" :: "r"(addr), "r"(count) : "memory");
}
__device__ __forceinline__ void mbar_arrive_remote(uint32_t addr){
    asm volatile("mbarrier.arrive.release.cluster.shared::cluster.b64 _, [%0];"
                 :: "r"(addr) : "memory");
}
__device__ __forceinline__ void mbar_wait_parity(uint32_t addr, uint32_t parity){
    uint32_t done;
    asm volatile(
        "{\n\t.reg .pred p;\n\t"
        "mbarrier.try_wait.parity.acquire.cluster.shared::cta.b64 p, [%1], %2;\n\t"
        "selp.b32 %0, 1, 0, p;\n\t}"
        : "=r"(done) : "r"(addr), "r"(parity) : "memory");
    while (!done) {
        asm volatile(
            "{\n\t.reg .pred p;\n\t"
            "mbarrier.try_wait.parity.acquire.cluster.shared::cta.b64 p, [%1], %2, 0x989680;\n\t"
            "selp.b32 %0, 1, 0, p;\n\t}"
            : "=r"(done) : "r"(addr), "r"(parity) : "memory");
    }
}
__device__ __forceinline__ void cluster_sync(){
    asm volatile("barrier.cluster.arrive.aligned;" ::: "memory");
    asm volatile("barrier.cluster.wait.aligned;"   ::: "memory");
}

// ---------------------------------------------------------------------------
// Input projection: xp[b,s,g] = emb[tok[b,s]] @ Wih[g,:] + bih[g] + bhh[g]
// ---------------------------------------------------------------------------
__global__ __launch_bounds__(256) void xproj_kernel(
    const int* __restrict__ toks, const float* __restrict__ emb,
    const float* __restrict__ Wih, const float* __restrict__ bih,
    const float* __restrict__ bhh, float* __restrict__ xp)
{
    __shared__ float xs[32][Dq];
    __shared__ int   tk[32];
    int row0 = blockIdx.x * 32;
    int j = threadIdx.x;

    if (j < 32) tk[j] = toks[row0 + j];
    __syncthreads();
    for (int i = j; i < 32*Dq; i += 256) {
        int r = i / Dq, k = i % Dq;
        xs[r][k] = emb[tk[r]*Dq + k];
    }

    float w[Dq];
#pragma unroll
    for (int k = 0; k < Dq; k++) w[k] = Wih[j*Dq + k];
    float bias = bih[j] + bhh[j];
    __syncthreads();

#pragma unroll 4
    for (int r = 0; r < 32; r++) {
        float acc = bias;
#pragma unroll
        for (int k = 0; k < Dq; k++) acc += w[k]*xs[r][k];
        xp[(row0 + r)*Gq + j] = acc;
    }
}

// ---------------------------------------------------------------------------
// Recurrent LSTM (R6 exact — best measured): one CTA per b, 256 threads.
// ---------------------------------------------------------------------------
__global__ __launch_bounds__(256) void lstm_kernel(
    const float* __restrict__ xp, const float* __restrict__ Whh,
    const int* __restrict__ iidx, int mode)
{
    __shared__ __align__(16) float hs[Eq];
    __shared__ float gs[Gq];

    int b = blockIdx.x, j = threadIdx.x;
    float* oh = mode ? g_out : g_h1;
    float* oc = mode ? nullptr : g_c1;

    float whh[Eq];
#pragma unroll
    for (int k = 0; k < Eq; k++) whh[k] = Whh[j*Eq + k];

    float c = 0.f;
    if (j < Eq) {
        float h0 = 0.f;
        if (mode) {
            int idx = iidx[b*Eq + j];          // s1_len is (B,1,E)
            h0 = g_h1[(b*Sq + idx)*Eq + j];
            c  = g_c1[(b*Sq + idx)*Eq + j];
        }
        hs[j] = h0;
    }
    __syncthreads();

    const float* xpb = xp + (size_t)b*Sq*Gq + j;
    float xv = xpb[0];

    for (int t = 0; t < Sq; t++) {
        const float4* h4 = (const float4*)hs;
        float a0 = xv, a1 = 0.f, a2 = 0.f, a3 = 0.f;
#pragma unroll
        for (int k = 0; k < 4; k++) {
            float4 v0 = h4[4*k], v1 = h4[4*k+1], v2 = h4[4*k+2], v3 = h4[4*k+3];
            a0 += whh[16*k   ]*v0.x + whh[16*k+1 ]*v0.y + whh[16*k+2 ]*v0.z + whh[16*k+3 ]*v0.w;
            a1 += whh[16*k+4 ]*v1.x + whh[16*k+5 ]*v1.y + whh[16*k+6 ]*v1.z + whh[16*k+7 ]*v1.w;
            a2 += whh[16*k+8 ]*v2.x + whh[16*k+9 ]*v2.y + whh[16*k+10]*v2.z + whh[16*k+11]*v2.w;
            a3 += whh[16*k+12]*v3.x + whh[16*k+13]*v3.y + whh[16*k+14]*v3.z + whh[16*k+15]*v3.w;
        }
        float acc = (a0 + a1) + (a2 + a3);
        if (t + 1 < Sq) xv = xpb[(t+1)*Gq];    // prefetch next gate input
        gs[j] = acc;
        __syncthreads();

        if (j < Eq) {
            float ig = fsig(gs[j]);
            float fg = fsig(gs[Eq + j]);
            float gg = ftanh(gs[2*Eq + j]);
            float og = fsig(gs[3*Eq + j]);
            c = fg*c + ig*gg;
            float h = og*ftanh(c);
            hs[j] = h;
            oh[(b*Sq + t)*Eq + j] = h;
            if (oc) oc[(b*Sq + t)*Eq + j] = c;
        }
        __syncthreads();
    }
}

// ---------------------------------------------------------------------------
// base[b,s,:] = h1[b,s,:] @ wy + out[b,s,:] @ wh
// ---------------------------------------------------------------------------
__global__ __launch_bounds__(256) void base_kernel(
    const float* __restrict__ wy, const float* __restrict__ wh)
{
    __shared__ float wys[Eq*Eq], whs[Eq*Eq];
    __shared__ float ht[16][Eq], ot[16][Eq];

    int b  = blockIdx.y;
    int s0 = blockIdx.x * 16;
    int tid = threadIdx.x;

    for (int i = tid; i < Eq*Eq; i += 256) { wys[i] = wy[i]; whs[i] = wh[i]; }
    for (int i = tid; i < 16*Eq; i += 256) {
        int s = i >> 6, k = i & 63;
        ht[s][k] = g_h1 [(b*Sq + s0 + s)*Eq + k];
        ot[s][k] = g_out[(b*Sq + s0 + s)*Eq + k];
    }
    __syncthreads();

    int sl = tid >> 4;
    int e0 = (tid & 15) * 4;
    float acc[4] = {0.f, 0.f, 0.f, 0.f};
#pragma unroll 8
    for (int k = 0; k < Eq; k++) {
        float hv = ht[sl][k], ov = ot[sl][k];
#pragma unroll
        for (int u = 0; u < 4; u++)
            acc[u] += hv*wys[k*Eq + e0 + u] + ov*whs[k*Eq + e0 + u];
    }
    float* dst = &g_base[(b*Sq + s0 + sl)*Eq + e0];
#pragma unroll
    for (int u = 0; u < 4; u++) dst[u] = acc[u];
}

// ---------------------------------------------------------------------------
// Attention scan, 2-CTA cluster per batch row.
// LOOP-INVARIANT REGISTERS per thread: tb[32], wtb[32] (tanh(base), w-scaled)
// AND hreg[32] = h for this thread's (16 rows x 2 e-cols) p3 slice — h_sm is
// gone; p3 is pure shfl+FFMA. p2 uses quad-rcp batching (1 MUFU / 4 elems).
// ---------------------------------------------------------------------------
#define ATT_FLOATS (4 + 2*68 + 4 + 4*64 + 12*64 + 16)
#define ATT_SMEM   (ATT_FLOATS*4)

__global__ __launch_bounds__(384) __cluster_dims__(2, 1, 1)
void attn_kernel(
    const float* __restrict__ wvec, const float* __restrict__ wr,
    const float* __restrict__ wt,   const float* __restrict__ s1s)
{
    extern __shared__ float sm[];
    // sm[0..3]: mbarrier (8B) + pad
    float* imp    = sm + 4;              // 2*68 import slots (peer writes here)
    float* r_s    = imp + 2*68 + 4;      // 64 (16B aligned: 4+136+4 = 144)
    float* tr_s   = r_s + 64;            // 64  raw tanh(r@wr)
    float* wtr_s  = tr_s + 64;           // 64  w*tanh(r@wr)
    float* trwt_s = wtr_s + 64;          // 64  tanh(r@wt)
    float* part   = trwt_s + 64;         // 12*64
    float* red    = part + 12*64;        // 16

    int cta  = blockIdx.x;
    int b    = cta >> 1;
    uint32_t rank = cta & 1u;
    int tid  = threadIdx.x;
    int lane = tid & 31, wid = tid >> 5;

    uint32_t mbar_local  = smem_u32(sm);
    uint32_t mbar_remote = mapa_u32(mbar_local, rank ^ 1u);
    uint32_t imp_remote  = mapa_u32(smem_u32(imp), rank ^ 1u);

    if (tid == 0) mbar_init(mbar_local, 64);

    int half = lane & 1;
    int row  = wid*16 + (lane >> 1);     // p2 row for this thread (0..191)

    // p1 weights: thread tid<256 -> output o=tid>>1, rows hh*32..+32
    float wcol[32];
    float wv_o = 0.f;
    if (tid < 256) {
        int o = tid >> 1, hh = tid & 1;
        const float* wsrc = (o < 64) ? (wr + o) : (wt + o - 64);
#pragma unroll
        for (int k = 0; k < 32; k++) wcol[k] = wsrc[(hh*32 + k)*Eq];
        if (o < 64 && hh == 0) wv_o = wvec[o];
    }

    const int gofs = b*Sq*Eq + (int)rank*SL*Eq;

    // loop-invariant per-thread registers: raw tb and w-scaled wtb (p2 slice)
    float tb[32], wtb[32];
    {
        const float* bsrc = &g_base[gofs + row*Eq + half*32];
        const float* wsrc = wvec + half*32;
#pragma unroll
        for (int k = 0; k < 32; k++) {
            tb[k]  = ftanh(bsrc[k]);
            wtb[k] = wsrc[k]*tb[k];
        }
    }
    // loop-invariant h registers for p3: rows wid*16..+15, cols 2*lane..+1
    float hreg[32];
    {
        const float* hsrc = &g_h1[gofs + (wid*16)*Eq + lane*2];
#pragma unroll
        for (int si = 0; si < 16; si++) {
            float2 hv = *(const float2*)&hsrc[si*Eq];
            hreg[2*si]   = hv.x;
            hreg[2*si+1] = hv.y;
        }
    }
    float m1 = s1s[b*Sq + (int)rank*SL + row];
    if (tid < 64) r_s[tid] = 0.f;
    __syncthreads();
    cluster_sync();   // peer's mbarrier init visible before any remote arrive

    for (int t = 0; t < Sq; t++) {
        // p1: tr = tanh(r@wr) (+ w-scaled), trwt = tanh(r@wt); 2 thr/output
        if (tid < 256) {
            int o = tid >> 1, hh = tid & 1;
            const float4* r4 = (const float4*)(r_s + hh*32);
            float a0 = 0.f, a1 = 0.f;
#pragma unroll
            for (int q = 0; q < 8; q += 2) {
                float4 v0 = r4[q], v1 = r4[q+1];
                a0 += wcol[4*q  ]*v0.x + wcol[4*q+1]*v0.y
                    + wcol[4*q+2]*v0.z + wcol[4*q+3]*v0.w;
                a1 += wcol[4*q+4]*v1.x + wcol[4*q+5]*v1.y
                    + wcol[4*q+6]*v1.z + wcol[4*q+7]*v1.w;
            }
            float s_ = a0 + a1;
            s_ += __shfl_xor_sync(0xffffffffu, s_, 1);
            if (hh == 0) {
                float v = ftanh(s_);
                if (o < 64) { tr_s[o] = v; wtr_s[o] = wv_o*v; }
                else trwt_s[o-64] = v;
            }
        }
        __syncthreads();

        // p2: score for `row` (2 threads/row, 32 elems each), quad-rcp form
        float sc = 0.f;
        {
            const float4* tr4 = (const float4*)(tr_s  + half*32);
            const float4* wr4 = (const float4*)(wtr_s + half*32);
#pragma unroll
            for (int q = 0; q < 8; q++) {
                float4 tv = tr4[q], wv = wr4[q];
                float b0 = fmaf(tb[4*q  ], tv.x, 1.f);
                float b1 = fmaf(tb[4*q+1], tv.y, 1.f);
                float b2 = fmaf(tb[4*q+2], tv.z, 1.f);
                float b3 = fmaf(tb[4*q+3], tv.w, 1.f);
                float wa0 = wtb[4*q  ] + wv.x;
                float wa1 = wtb[4*q+1] + wv.y;
                float wa2 = wtb[4*q+2] + wv.z;
                float wa3 = wtb[4*q+3] + wv.w;
                float n01 = fmaf(wa1, b0, wa0*b1);
                float n23 = fmaf(wa3, b2, wa2*b3);
                float d01 = b0*b1, d23 = b2*b3;
                float num = fmaf(n23, d01, n01*d23);
                sc = fmaf(num, rcp_fast(d01*d23), sc);
            }
        }
        sc += __shfl_xor_sync(0xffffffffu, sc, 1);
        sc = m1*sc - (1.f - m1)*1e12f;
        float p = __expf(sc);

        // warp sum of p (each p duplicated in a lane pair -> halve)
        float v = p;
#pragma unroll
        for (int o = 16; o > 0; o >>= 1) v += __shfl_xor_sync(0xffffffffu, v, o);
        if (lane == 0) red[wid] = 0.5f*v;

        // p3: h.p partials from REGISTERS (16 rows x 2 e-cols per thread)
        {
            float a0 = 0.f, a1 = 0.f;
#pragma unroll
            for (int si = 0; si < 16; si++) {
                float pv = __shfl_sync(0xffffffffu, p, 2*si);
                a0 = fmaf(hreg[2*si],   pv, a0);
                a1 = fmaf(hreg[2*si+1], pv, a1);
            }
            part[wid*64 + lane*2]     = a0;
            part[wid*64 + lane*2 + 1] = a1;
        }
        __syncthreads();

        // p5: combine partials, exchange with peer, update r
        if (tid < 64) {
            float nl = 0.f;
#pragma unroll
            for (int g = 0; g < 12; g++) nl += part[g*64 + tid];
            float sl_ = 0.f;
#pragma unroll
            for (int i = 0; i < 12; i++) sl_ += red[i];

            int slot = (t & 1) * 68;
            st_cluster_f32(imp_remote + (slot + tid)*4, nl);
            if (tid == 0) st_cluster_f32(imp_remote + (slot + 64)*4, sl_);
            mbar_arrive_remote(mbar_remote);           // release (64 arrivals)
            mbar_wait_parity(mbar_local, (uint32_t)(t & 1));

            float pn = imp[slot + tid];
            float ps = imp[slot + 64];
            float rn = (nl + pn)*rcp_fast(sl_ + ps) + trwt_s[tid];
            r_s[tid] = rn;
            if (rank == 0) g_Rt[(b*Sq + t)*Eq + tid] = rn;
        }
        __syncthreads();
    }
    cluster_sync();   // no CTA exits while peer may still write our smem
}

// ---------------------------------------------------------------------------
// Final gathers + MLP head
// ---------------------------------------------------------------------------
__global__ __launch_bounds__(128) void final_kernel(
    const int* __restrict__ s2len,
    const float* __restrict__ wp, const float* __restrict__ wx,
    const float* __restrict__ l1W, const float* __restrict__ l1b,
    const float* __restrict__ lW,  const float* __restrict__ lb,
    float* __restrict__ outp)
{
    __shared__ float rn[64], hn[64], hid[64], h2[128];
    int b = blockIdx.x, tid = threadIdx.x;

    if (tid < 64) {
        int idx = s2len[b*64 + tid];
        rn[tid] = g_Rt [(b*Sq + idx)*Eq + tid];
        hn[tid] = g_out[(b*Sq + idx)*Eq + tid];
    }
    __syncthreads();
    if (tid < 64) {
        float a = 0.f;
#pragma unroll 8
        for (int e = 0; e < 64; e++)
            a += rn[e]*wp[e*64 + tid] + hn[e]*wx[e*64 + tid];
        hid[tid] = ftanh(a);
    }
    __syncthreads();
    {
        float a = l1b[tid];
#pragma unroll 8
        for (int f = 0; f < 64; f++) a += hid[f]*l1W[tid*64 + f];
        h2[tid] = ftanh(a);
    }
    __syncthreads();
    if (tid < 4) {
        float a = lb[tid];
#pragma unroll 8
        for (int j = 0; j < 128; j++) a += h2[j]*lW[tid*128 + j];
        outp[b*4 + tid] = a;
    }
}

// ---------------------------------------------------------------------------
extern "C" void kernel_launch(void* const* d_in, const int* in_sizes, int n_in,
                              void* d_out, int out_size)
{
    (void)in_sizes; (void)n_in; (void)out_size;

    const int*   s1   = (const int*)d_in[0];
    const int*   s2   = (const int*)d_in[1];
    const int*   s1l  = (const int*)d_in[2];
    const int*   s2l  = (const int*)d_in[3];
    const float* s1s  = (const float*)d_in[4];
    /* d_in[5] = s2_s, unused by the reference */
    const float* emb  = (const float*)d_in[6];
    const float* Wih1 = (const float*)d_in[7];
    const float* Whh1 = (const float*)d_in[8];
    const float* bih1 = (const float*)d_in[9];
    const float* bhh1 = (const float*)d_in[10];
    const float* Wih2 = (const float*)d_in[11];
    const float* Whh2 = (const float*)d_in[12];
    const float* bih2 = (const float*)d_in[13];
    const float* bhh2 = (const float*)d_in[14];
    const float* wy   = (const float*)d_in[15];
    const float* wh   = (const float*)d_in[16];
    const float* wv   = (const float*)d_in[17];
    const float* wp   = (const float*)d_in[18];
    const float* wx   = (const float*)d_in[19];
    const float* wr   = (const float*)d_in[20];
    const float* wt   = (const float*)d_in[21];
    const float* l1W  = (const float*)d_in[22];
    const float* l1b  = (const float*)d_in[23];
    const float* lW   = (const float*)d_in[24];
    const float* lb   = (const float*)d_in[25];
    float* outp = (float*)d_out;

    cudaFuncSetAttribute(attn_kernel,
                         cudaFuncAttributeMaxDynamicSharedMemorySize, ATT_SMEM);

    float* xp1; cudaGetSymbolAddress((void**)&xp1, g_xp1);
    float* xp2; cudaGetSymbolAddress((void**)&xp2, g_xp2);

    xproj_kernel<<<(Bq*Sq)/32, 256>>>(s1, emb, Wih1, bih1, bhh1, xp1);
    xproj_kernel<<<(Bq*Sq)/32, 256>>>(s2, emb, Wih2, bih2, bhh2, xp2);
    lstm_kernel<<<Bq, 256>>>(xp1, Whh1, nullptr, 0);
    lstm_kernel<<<Bq, 256>>>(xp2, Whh2, s1l, 1);
    base_kernel<<<dim3(24, Bq), 256>>>(wy, wh);
    attn_kernel<<<Bq*2, 384, ATT_SMEM>>>(wv, wr, wt, s1s);
    final_kernel<<<Bq, 128>>>(s2l, wp, wx, l1W, l1b, lW, lb, outp);
}